// round 11
// baseline (speedup 1.0000x reference)
#include <cuda_runtime.h>
#include <math.h>
#include <stdint.h>

#define BATCH 8
#define SEQ   256
#define F0    512
#define F1    256
#define F2    128
#define KMAX  30
#define DPB   8       // dpscan blocks per batch (32 rows each)
#define SMB   16      // softmax blocks per batch

// ---- scratch (__device__ globals; no allocations allowed) ----
__device__ float g_h[BATCH*SEQ*F1];
__device__ float g_z[BATCH*SEQ*F2];
__device__ float g_corr[BATCH*SEQ*SEQ];
__device__ float g_P[BATCH*SEQ*SEQ];
__device__ float g_Pt[BATCH*SEQ*SEQ];       // transpose of P
__device__ float g_Pdiag[BATCH][SEQ];       // P[i][i]
__device__ float g_diag[BATCH][SEQ];        // diag of corr
__device__ float g_seg[BATCH][DPB][SEQ];    // per-segment row-scan totals
__device__ float g_Cc[KMAX][BATCH][SEQ];    // DP C-vectors
__device__ int   g_flagS[BATCH][DPB];       // seg totals ready
__device__ int   g_flagP[BATCH][DPB];       // P rows of segment ready
__device__ int   g_flagC[BATCH][KMAX][DPB]; // DP chunk ready
__device__ float g_part[BATCH][SMB][SEQ];   // softmax partials

// dpscan dynamic smem layout (floats)
#define SC_OFF   0                    // sC[KMAX][258]      7740
#define T_OFF    7740                 // T[32][256]         8192
#define QOFF_OFF 15932                // OFFQ[4][256]       1024
#define OFF_OFF  16956                // OFF[256]            256
#define SDN_OFF  17212                // sdn[32]              32
#define DSM_FLOATS 17244
#define DSM_BYTES  (DSM_FLOATS*4)

// ============================================================
// GEMM: C[M,N] = (A[M,K] @ B[K,N]) + bias, optional relu.
// 64x64 tile, BK=16, 256 threads, 4x4 per thread. Scalar FFMA.
// ============================================================
template<int RELU>
__global__ __launch_bounds__(256) void gemm_kernel(
    const float* __restrict__ A, const float* __restrict__ B,
    const float* __restrict__ bias, float* __restrict__ C,
    int M, int N, int K)
{
    __shared__ float As[16][64];   // As[k][m]
    __shared__ float Bs[16][64];   // Bs[k][n]
    const int m0 = blockIdx.y * 64, n0 = blockIdx.x * 64;
    const int tid = threadIdx.x;
    const int ty = tid >> 4, tx = tid & 15;
    const int arow = tid >> 2, akq = tid & 3;
    const int bkr  = tid >> 4, bnq = tid & 15;

    float acc[4][4] = {};

    for (int k0 = 0; k0 < K; k0 += 16) {
        float4 va = *(const float4*)(A + (size_t)(m0 + arow) * K + k0 + akq * 4);
        As[akq*4+0][arow] = va.x; As[akq*4+1][arow] = va.y;
        As[akq*4+2][arow] = va.z; As[akq*4+3][arow] = va.w;
        float4 vb = *(const float4*)(B + (size_t)(k0 + bkr) * N + n0 + bnq * 4);
        *(float4*)&Bs[bkr][bnq*4] = vb;
        __syncthreads();
        #pragma unroll
        for (int k = 0; k < 16; k++) {
            float4 a4 = *(const float4*)&As[k][ty*4];
            float4 b4 = *(const float4*)&Bs[k][tx*4];
            float av[4] = {a4.x, a4.y, a4.z, a4.w};
            float bv[4] = {b4.x, b4.y, b4.z, b4.w};
            #pragma unroll
            for (int r = 0; r < 4; r++)
                #pragma unroll
                for (int c = 0; c < 4; c++)
                    acc[r][c] += av[r] * bv[c];
        }
        __syncthreads();
    }

    #pragma unroll
    for (int r = 0; r < 4; r++) {
        int m = m0 + ty*4 + r;
        #pragma unroll
        for (int c = 0; c < 4; c++) {
            int n = n0 + tx*4 + c;
            float v = acc[r][c] + bias[n];
            if (RELU) v = fmaxf(v, 0.0f);
            C[(size_t)m * N + n] = v;
        }
    }
}

// ============================================================
// corr[b] = z_b @ z_b^T (NT, M=N=256, K=128), scalar FFMA.
// Captures diag; block (0,0,0) zeroes all pipeline flags.
// ============================================================
__global__ __launch_bounds__(256) void syrk_kernel()
{
    __shared__ float As[16][64];
    __shared__ float Bs[16][64];
    const int bz = blockIdx.z;
    const float* Z = g_z + (size_t)bz * SEQ * F2;
    float* C = g_corr + (size_t)bz * SEQ * SEQ;
    const int m0 = blockIdx.y * 64, n0 = blockIdx.x * 64;
    const int tid = threadIdx.x;
    const int ty = tid >> 4, tx = tid & 15;
    const int row = tid >> 2, kq = tid & 3;

    if (blockIdx.x == 0 && blockIdx.y == 0 && bz == 0) {
        for (int i = tid; i < BATCH*DPB; i += 256) {
            ((int*)g_flagS)[i] = 0;
            ((int*)g_flagP)[i] = 0;
        }
        for (int i = tid; i < BATCH*KMAX*DPB; i += 256)
            ((int*)g_flagC)[i] = 0;
    }

    float acc[4][4] = {};

    for (int k0 = 0; k0 < F2; k0 += 16) {
        float4 va = *(const float4*)(Z + (size_t)(m0 + row) * F2 + k0 + kq * 4);
        As[kq*4+0][row] = va.x; As[kq*4+1][row] = va.y;
        As[kq*4+2][row] = va.z; As[kq*4+3][row] = va.w;
        float4 vb = *(const float4*)(Z + (size_t)(n0 + row) * F2 + k0 + kq * 4);
        Bs[kq*4+0][row] = vb.x; Bs[kq*4+1][row] = vb.y;
        Bs[kq*4+2][row] = vb.z; Bs[kq*4+3][row] = vb.w;
        __syncthreads();
        #pragma unroll
        for (int k = 0; k < 16; k++) {
            float4 a4 = *(const float4*)&As[k][ty*4];
            float4 b4 = *(const float4*)&Bs[k][tx*4];
            float av[4] = {a4.x, a4.y, a4.z, a4.w};
            float bv[4] = {b4.x, b4.y, b4.z, b4.w};
            #pragma unroll
            for (int r = 0; r < 4; r++)
                #pragma unroll
                for (int c = 0; c < 4; c++)
                    acc[r][c] += av[r] * bv[c];
        }
        __syncthreads();
    }

    #pragma unroll
    for (int r = 0; r < 4; r++) {
        int m = m0 + ty*4 + r;
        #pragma unroll
        for (int c = 0; c < 4; c++) {
            int n = n0 + tx*4 + c;
            C[(size_t)m * SEQ + n] = acc[r][c];
            if (m == n) g_diag[bz][m] = acc[r][c];
        }
    }
}

// ============================================================
// dpscan: fused D+scan -> P/Pt/Pdiag -> row build -> pipelined
// min-DP. Grid (BATCH, DPB), 1024 threads. All cross-block deps
// via per-(stage,chunk) flags; no full barriers anywhere.
//   phase1: quarter q (tid>>8) x column i (tid&255), 8 rows each.
//   colscan deps: seg totals of blocks < g.
//   rowbuild deps: P rows of blocks >= g-1.
//   DP step kk deps: C chunks kk-1 of blocks > g.
// ============================================================
__global__ __launch_bounds__(1024) void dpscan_kernel()
{
    extern __shared__ float sm[];
    float (*sC)[258]   = (float(*)[258])(sm + SC_OFF);
    float (*T)[SEQ]    = (float(*)[SEQ])(sm + T_OFF);
    float (*OFFQ)[SEQ] = (float(*)[SEQ])(sm + QOFF_OFF);
    float *OFF         = sm + OFF_OFF;
    float *sdn         = sm + SDN_OFF;

    const int b = blockIdx.x, g = blockIdx.y;
    const int tid = threadIdx.x, w = tid >> 5, l = tid & 31;
    const int n0 = g * 32;

    // ---- phase 1: D + within-quarter row-scan ----
    if (tid < 32) sdn[tid] = g_diag[b][n0 + tid];
    __syncthreads();
    {
        const int i = tid & 255, q = tid >> 8;
        const float di = g_diag[b][i];
        const float* cb = g_corr + (size_t)b * SEQ * SEQ + (size_t)(n0 + q*8) * SEQ;
        float run = 0.0f;
        #pragma unroll
        for (int r = 0; r < 8; r++) {
            float denom = sqrtf(fmaxf(sdn[q*8 + r] * di, 1e-8f));
            float d = (1.0f - cb[r*SEQ + i] / denom) * 0.5f;
            run += d;
            T[q*8 + r][i] = run;
        }
        OFFQ[q][i] = run;          // quarter total (transformed below)
    }
    __syncthreads();
    if (tid < 256) {
        const int i = tid;
        float t0 = OFFQ[0][i], t1 = OFFQ[1][i], t2 = OFFQ[2][i], t3 = OFFQ[3][i];
        float o1 = t0, o2 = t0 + t1, o3 = o2 + t2;
        OFFQ[0][i] = 0.0f; OFFQ[1][i] = o1; OFFQ[2][i] = o2; OFFQ[3][i] = o3;
        __stcg(&g_seg[b][g][i], o3 + t3);
    }
    __syncthreads();
    if (tid == 0) { __threadfence(); *(volatile int*)&g_flagS[b][g] = 1; }

    // ---- wait seg totals of lower blocks; build OFF ----
    if (w == 0 && l < g) {
        volatile int* f = &g_flagS[b][l];
        while (*f == 0) { }
    }
    if (w == 0) { __syncwarp(); if (l == 0) __threadfence(); }
    __syncthreads();
    if (tid < 256) {
        float o = 0.0f;
        for (int gp = 0; gp < g; gp++) o += __ldcg(&g_seg[b][gp][tid]);
        OFF[tid] = o;
    }
    __syncthreads();

    // ---- col-scan: warp w scans absolute row n0+w ----
    {
        const int row = n0 + w;
        const int q = w >> 3;
        float v[8];
        #pragma unroll
        for (int j = 0; j < 8; j++) {
            int c = l*8 + j;
            v[j] = T[w][c] + OFFQ[q][c] + OFF[c];
        }
        #pragma unroll
        for (int j = 1; j < 8; j++) v[j] += v[j-1];
        float tot = v[7], inc = tot;
        #pragma unroll
        for (int d2 = 1; d2 < 32; d2 <<= 1) {
            float t2 = __shfl_up_sync(0xffffffffu, inc, d2);
            if (l >= d2) inc += t2;
        }
        float excl = inc - tot;
        #pragma unroll
        for (int j = 0; j < 8; j++) v[j] += excl;
        float* P = g_P + ((size_t)b * SEQ + row) * SEQ;
        #pragma unroll
        for (int j = 0; j < 8; j++) __stcg(&P[l*8 + j], v[j]);
        float* Pt = g_Pt + (size_t)b * SEQ * SEQ;
        #pragma unroll
        for (int j = 0; j < 8; j++) {
            int i = l*8 + j;
            __stcg(&Pt[(size_t)i * SEQ + row], v[j]);
            if (i == row) __stcg(&g_Pdiag[b][row], v[j]);
        }
    }
    __syncthreads();
    if (tid == 0) { __threadfence(); *(volatile int*)&g_flagP[b][g] = 1; }

    // ---- wait P of blocks >= g-1 (incl. own, already set) ----
    {
        const int lo = (g > 0) ? (g - 1) : 0;
        if (w == 0 && l >= lo && l < DPB) {
            volatile int* f = &g_flagP[b][l];
            while (*f == 0) { }
        }
        if (w == 0) { __syncwarp(); if (l == 0) __threadfence(); }
        __syncthreads();
    }

    // ---- build Ds row wb = n0+w from 4-corner formula ----
    const int wb = n0 + w;
    const float* P  = g_P  + (size_t)b * SEQ * SEQ;
    const float* Pt = g_Pt + (size_t)b * SEQ * SEQ;
    float rowv[8];
    {
        const float pd = (wb == 0) ? 0.0f : __ldcg(&g_Pdiag[b][wb-1]);
        const float* Prow  = P  + (size_t)(wb-1) * SEQ;
        const float* Ptrow = Pt + (size_t)(wb-1) * SEQ;
        #pragma unroll
        for (int j = 0; j < 8; j++) {
            int i = l + 32*j;
            if (i >= wb) {
                float a  = __ldcg(&g_Pdiag[b][i]);
                float bb = (wb == 0) ? 0.0f : __ldcg(&Prow[i]);
                float cc = (wb == 0) ? 0.0f : __ldcg(&Ptrow[i]);
                rowv[j] = ((a - bb) - cc) + pd;
            } else {
                rowv[j] = 3.0e38f;
            }
        }
    }

    // ---- publish own chunk of C0 = Ds[.,255] ----
    if (l == 31) { sC[0][wb] = rowv[7]; __stcg(&g_Cc[0][b][wb], rowv[7]); }
    __syncthreads();
    if (tid == 0) { __threadfence(); *(volatile int*)&g_flagC[b][0][g] = 1; }

    // ---- pipelined min-DP: 29 steps ----
    #pragma unroll 1
    for (int kk = 1; kk < KMAX; kk++) {
        if (w == 0) {
            if (l < DPB && l > g) {
                volatile int* f = &g_flagC[b][kk-1][l];
                while (*f == 0) { }
            }
            __syncwarp();
            if (l == 0) __threadfence();
        }
        __syncthreads();
        if (tid >= (g + 1) * 32 && tid < SEQ)
            sC[kk-1][tid] = __ldcg(&g_Cc[kk-1][b][tid]);
        __syncthreads();

        const int limit = SEQ - kk;
        float val = 0.0f;
        if (wb < limit) {
            float mn = 3.0e38f;
            #pragma unroll
            for (int j = 0; j < 8; j++) {
                int i = l + 32*j;
                float t = (i < limit) ? (rowv[j] + sC[kk-1][i + 1]) : 3.0e38f;
                mn = fminf(mn, t);
            }
            #pragma unroll
            for (int o = 16; o > 0; o >>= 1)
                mn = fminf(mn, __shfl_xor_sync(0xffffffffu, mn, o));
            val = mn;
        }
        if (l == 0) { sC[kk][wb] = val; __stcg(&g_Cc[kk][b][wb], val); }
        __syncthreads();
        if (tid == 0) { __threadfence(); *(volatile int*)&g_flagC[b][kk][g] = 1; }
    }
}

// ============================================================
// softmax: grid (BATCH, SMB), 512 thr, warp = row (interleaved).
// exp skipped per 32-wide group when all lanes underflow.
// ============================================================
__global__ __launch_bounds__(512) void softmax_kernel()
{
    __shared__ float sC[KMAX][SEQ + 2];
    __shared__ float sacc[16][SEQ];
    const int b = blockIdx.x, blk = blockIdx.y;
    const int tid = threadIdx.x, w = tid >> 5, l = tid & 31;
    const int wb = w * 16 + blk;
    const float* P  = g_P  + (size_t)b * SEQ * SEQ;
    const float* Pt = g_Pt + (size_t)b * SEQ * SEQ;

    for (int idx = tid; idx < KMAX*SEQ; idx += 512)
        sC[idx >> 8][idx & 255] = g_Cc[idx >> 8][b][idx & 255];

    float rowv[8];
    {
        const float pd = (wb == 0) ? 0.0f : g_Pdiag[b][wb-1];
        const float* Prow  = P  + (size_t)(wb-1) * SEQ;
        const float* Ptrow = Pt + (size_t)(wb-1) * SEQ;
        #pragma unroll
        for (int j = 0; j < 8; j++) {
            int i = l + 32*j;
            if (i >= wb) {
                float a  = g_Pdiag[b][i];
                float bb = (wb == 0) ? 0.0f : Prow[i];
                float cc = (wb == 0) ? 0.0f : Ptrow[i];
                rowv[j] = ((a - bb) - cc) + pd;
            } else {
                rowv[j] = 3.0e38f;
            }
        }
    }
    __syncthreads();

    float acc[8] = {};
    #pragma unroll 1
    for (int kk = 1; kk < KMAX; kk++) {
        const int limit = SEQ - kk;
        if (wb >= limit) break;
        const float mn = sC[kk][wb];
        const float* sCp = sC[kk-1];
        float e[8];
        float s = 0.0f;
        #pragma unroll
        for (int j = 0; j < 8; j++) {
            e[j] = 0.0f;
            if (32*j + 31 >= wb && 32*j < limit) {
                int i = l + 32*j;
                float x = (i < limit) ? ((mn - rowv[j]) - sCp[i + 1]) : -1.0e30f;
                if (__any_sync(0xffffffffu, x > -87.0f)) {
                    e[j] = __expf(x);
                    s += e[j];
                }
            }
        }
        #pragma unroll
        for (int o = 16; o > 0; o >>= 1)
            s += __shfl_xor_sync(0xffffffffu, s, o);
        float inv = __fdividef(1.0f, s);
        #pragma unroll
        for (int j = 0; j < 8; j++) acc[j] += e[j] * inv;
    }

    #pragma unroll
    for (int j = 0; j < 8; j++) sacc[w][l + 32*j] = acc[j];
    __syncthreads();
    if (tid < SEQ) {
        float sum = 0.0f;
        #pragma unroll
        for (int ww = 0; ww < 16; ww++) sum += sacc[ww][tid];
        g_part[b][blk][tid] = sum;
    }
}

// out[b][i] = (sum of partials + k0 term) / exact mask count
__global__ __launch_bounds__(256) void finalize_kernel(float* __restrict__ out)
{
    const int b = blockIdx.x, i = threadIdx.x;
    float num = (i == SEQ - 1) ? (float)SEQ : 0.0f;
    #pragma unroll
    for (int p = 0; p < SMB; p++) num += g_part[b][p][i];
    int m = min(KMAX - 1, SEQ - 1 - i);
    float cnt = (float)((i + 1) * m + ((i == SEQ - 1) ? SEQ : 0));
    out[b*SEQ + i] = num / cnt;
}

// ============================================================
extern "C" void kernel_launch(void* const* d_in, const int* in_sizes, int n_in,
                              void* d_out, int out_size)
{
    const float* x  = (const float*)d_in[0];
    const float* W0 = (const float*)d_in[1];
    const float* b0 = (const float*)d_in[2];
    const float* W1 = (const float*)d_in[3];
    const float* b1 = (const float*)d_in[4];
    float* out = (float*)d_out;

    static float* p_h = nullptr;
    static float* p_z = nullptr;
    if (!p_h) {
        cudaGetSymbolAddress((void**)&p_h, g_h);
        cudaGetSymbolAddress((void**)&p_z, g_z);
        cudaFuncSetAttribute(dpscan_kernel,
                             cudaFuncAttributeMaxDynamicSharedMemorySize, DSM_BYTES);
    }

    gemm_kernel<1><<<dim3(F1/64, (BATCH*SEQ)/64), 256>>>(x,   W0, b0, p_h, BATCH*SEQ, F1, F0);
    gemm_kernel<0><<<dim3(F2/64, (BATCH*SEQ)/64), 256>>>(p_h, W1, b1, p_z, BATCH*SEQ, F2, F1);
    syrk_kernel    <<<dim3(SEQ/64, SEQ/64, BATCH), 256>>>();
    dpscan_kernel  <<<dim3(BATCH, DPB), 1024, DSM_BYTES>>>();
    softmax_kernel <<<dim3(BATCH, SMB), 512>>>();
    finalize_kernel<<<BATCH, SEQ>>>(out);
}